// round 2
// baseline (speedup 1.0000x reference)
#include <cuda_runtime.h>
#include <math.h>
#include <stdint.h>

#define QQ 1024
#define BB 8
#define DD 1024
#define HH 16
#define DHH 64
#define FFF 4096
#define MM (QQ*BB)          /* 8192 rows (q*B+b) */

// ---------------- scratch (__device__ globals: the sanctioned alloc-free path) ----------------
__device__ float g_qkv [(size_t)MM * 3 * DD];      // 96 MB  [m][3D]
__device__ float g_qc  [(size_t)MM * DD];          // wq + r_w_bias
__device__ float g_qr  [(size_t)MM * DD];          // wq + r_r_bias
__device__ float g_rk  [(size_t)QQ * DD];          // pos_emb @ r_w
__device__ float g_AC  [(size_t)BB * HH * QQ * QQ];// 512 MB scores / probs (in-place)
__device__ float g_BD  [(size_t)BB * HH * QQ * QQ];// 512 MB rel scores
__device__ float g_y   [(size_t)MM * DD];          // LN outputs (reused)
__device__ float g_attn[(size_t)MM * DD];          // attention output
__device__ float g_xa  [(size_t)MM * DD];          // x + attn@o_w
__device__ float g_hid [(size_t)MM * FFF];         // 128 MB FFN hidden

// ---------------- block reductions ----------------
__device__ __forceinline__ float blockSum(float v, float* sbuf) {
    int t = threadIdx.x;
#pragma unroll
    for (int o = 16; o > 0; o >>= 1) v += __shfl_xor_sync(0xffffffffu, v, o);
    __syncthreads();
    if ((t & 31) == 0) sbuf[t >> 5] = v;
    __syncthreads();
    float s = 0.f;
#pragma unroll
    for (int w = 0; w < 8; w++) s += sbuf[w];
    return s;
}
__device__ __forceinline__ float blockMax(float v, float* sbuf) {
    int t = threadIdx.x;
#pragma unroll
    for (int o = 16; o > 0; o >>= 1) v = fmaxf(v, __shfl_xor_sync(0xffffffffu, v, o));
    __syncthreads();
    if ((t & 31) == 0) sbuf[t >> 5] = v;
    __syncthreads();
    float s = -1e30f;
#pragma unroll
    for (int w = 0; w < 8; w++) s = fmaxf(s, sbuf[w]);
    return s;
}

// ---------------- LayerNorm: one block per row of 1024 ----------------
__global__ __launch_bounds__(256) void ln_kernel(const float* __restrict__ X,
                                                 const float* __restrict__ g,
                                                 const float* __restrict__ b,
                                                 float* __restrict__ Y) {
    __shared__ float sbuf[8];
    int row = blockIdx.x, t = threadIdx.x;
    const float* xr = X + (size_t)row * DD;
    float v[4]; float s = 0.f;
#pragma unroll
    for (int r = 0; r < 4; r++) { v[r] = xr[t + r * 256]; s += v[r]; }
    s = blockSum(s, sbuf);
    float mu = s * (1.0f / DD);
    float s2 = 0.f;
#pragma unroll
    for (int r = 0; r < 4; r++) { v[r] -= mu; s2 += v[r] * v[r]; }
    s2 = blockSum(s2, sbuf);
    float rs = rsqrtf(s2 * (1.0f / DD) + 1e-5f);
    float* yr = Y + (size_t)row * DD;
#pragma unroll
    for (int r = 0; r < 4; r++) {
        int j = t + r * 256;
        yr[j] = v[r] * rs * g[j] + b[j];
    }
}

// ---------------- qc = wq + r_w_bias ; qr = wq + r_r_bias (flat 1024 biases) ----------------
__global__ __launch_bounds__(256) void prep_kernel(const float* __restrict__ qkv,
                                                   const float* __restrict__ rwb,
                                                   const float* __restrict__ rrb,
                                                   float* __restrict__ qc,
                                                   float* __restrict__ qr) {
    int e4 = blockIdx.x * 256 + threadIdx.x;      // over MM*DD/4 float4s
    int m = e4 >> 8;
    int c = (e4 & 255) << 2;
    float4 v = *(const float4*)(qkv + (size_t)m * 3072 + c);
    float4 wb = *(const float4*)(rwb + c);
    float4 rb = *(const float4*)(rrb + c);
    float4 oc = make_float4(v.x + wb.x, v.y + wb.y, v.z + wb.z, v.w + wb.w);
    float4 orr = make_float4(v.x + rb.x, v.y + rb.y, v.z + rb.z, v.w + rb.w);
    *(float4*)(qc + (size_t)m * DD + c) = oc;
    *(float4*)(qr + (size_t)m * DD + c) = orr;
}

// ---------------- generic tiled SGEMM: C = A[M,K] @ W[K,N] (+bias)(+relu)(+res) ----------------
#define GBM 128
#define GBN 128
#define GKT 16
#define FL_BIAS 1
#define FL_RELU 2
#define FL_RES  4

__global__ __launch_bounds__(256) void gemm_kernel(const float* __restrict__ A,
                                                   const float* __restrict__ W,
                                                   float* __restrict__ C,
                                                   const float* __restrict__ bias,
                                                   const float* __restrict__ res,
                                                   int M, int N, int K, int flags) {
    __shared__ float As[GKT][GBM + 4];   // [k][m]
    __shared__ float Bs[GKT][GBN + 4];   // [k][n]
    int t = threadIdx.x;
    int m0 = blockIdx.y * GBM, n0 = blockIdx.x * GBN;
    int tx = t & 15, ty = t >> 4;
    float acc[8][8];
#pragma unroll
    for (int i = 0; i < 8; i++)
#pragma unroll
        for (int j = 0; j < 8; j++) acc[i][j] = 0.f;

    for (int k0 = 0; k0 < K; k0 += GKT) {
#pragma unroll
        for (int rep = 0; rep < 2; rep++) {
            int idx = t + rep * 256;
            int ar = idx >> 2, ac4 = (idx & 3) << 2;
            float4 va = *(const float4*)(A + (size_t)(m0 + ar) * K + k0 + ac4);
            As[ac4 + 0][ar] = va.x; As[ac4 + 1][ar] = va.y;
            As[ac4 + 2][ar] = va.z; As[ac4 + 3][ar] = va.w;
            int br = idx >> 5, bc4 = (idx & 31) << 2;
            float4 vb = *(const float4*)(W + (size_t)(k0 + br) * N + n0 + bc4);
            *(float4*)&Bs[br][bc4] = vb;
        }
        __syncthreads();
#pragma unroll
        for (int k = 0; k < GKT; k++) {
            float a[8], bb[8];
            *(float4*)(a)     = *(const float4*)&As[k][ty * 8];
            *(float4*)(a + 4) = *(const float4*)&As[k][ty * 8 + 4];
            *(float4*)(bb)     = *(const float4*)&Bs[k][tx * 8];
            *(float4*)(bb + 4) = *(const float4*)&Bs[k][tx * 8 + 4];
#pragma unroll
            for (int ii = 0; ii < 8; ii++)
#pragma unroll
                for (int jj = 0; jj < 8; jj++)
                    acc[ii][jj] = fmaf(a[ii], bb[jj], acc[ii][jj]);
        }
        __syncthreads();
    }

#pragma unroll
    for (int ii = 0; ii < 8; ii++) {
        int m = m0 + ty * 8 + ii;
#pragma unroll
        for (int j4 = 0; j4 < 8; j4 += 4) {
            int n = n0 + tx * 8 + j4;
            float4 o = make_float4(acc[ii][j4], acc[ii][j4 + 1], acc[ii][j4 + 2], acc[ii][j4 + 3]);
            if (flags & FL_BIAS) {
                float4 bv = *(const float4*)(bias + n);
                o.x += bv.x; o.y += bv.y; o.z += bv.z; o.w += bv.w;
            }
            if (flags & FL_RELU) {
                o.x = fmaxf(o.x, 0.f); o.y = fmaxf(o.y, 0.f);
                o.z = fmaxf(o.z, 0.f); o.w = fmaxf(o.w, 0.f);
            }
            if (flags & FL_RES) {
                float4 rv = *(const float4*)(res + (size_t)m * N + n);
                o.x += rv.x; o.y += rv.y; o.z += rv.z; o.w += rv.w;
            }
            *(float4*)(C + (size_t)m * N + n) = o;
        }
    }
}

// ---------------- batched score GEMM: C[bz][i][j] = sum_d A[i,d] * B[j,d], K=64 ----------------
// A element: A + b*a_bs + h*64 + i*a_rs + d ;  B element: B + b*b_bs + h*64 + j*b_rs + d
__global__ __launch_bounds__(256) void score_kernel(const float* __restrict__ A, int a_bs, int a_rs,
                                                    const float* __restrict__ Bm, int b_bs, int b_rs,
                                                    float* __restrict__ C) {
    __shared__ float As[64 * 64];   // [k][i] XOR-swizzled in 4-float quads
    __shared__ float Bs[64 * 64];   // [k][j] XOR-swizzled
    int t = threadIdx.x;
    int bz = blockIdx.z, b = bz >> 4, h = bz & 15;
    int i0 = blockIdx.y << 6, j0 = blockIdx.x << 6;
    const float* Ab = A + (size_t)b * a_bs + h * 64;
    const float* Bb = Bm + (size_t)b * b_bs + h * 64;

#pragma unroll
    for (int rep = 0; rep < 4; rep++) {
        int idx = t + rep * 256;
        int r = idx >> 4, c4 = (idx & 15) << 2;     // row 0..63, k-quad base
        int r4 = r >> 2, rm = r & 3;
        float4 va = *(const float4*)(Ab + (size_t)(i0 + r) * a_rs + c4);
        float4 vb = *(const float4*)(Bb + (size_t)(j0 + r) * b_rs + c4);
#pragma unroll
        for (int u = 0; u < 4; u++) {
            int kk = c4 + u;
            int off = kk * 64 + (((r4 ^ (kk & 15)) << 2) + rm);
            float av = (u == 0) ? va.x : (u == 1) ? va.y : (u == 2) ? va.z : va.w;
            float bv = (u == 0) ? vb.x : (u == 1) ? vb.y : (u == 2) ? vb.z : vb.w;
            As[off] = av;
            Bs[off] = bv;
        }
    }
    __syncthreads();

    int tx = t & 15, ty = t >> 4;
    float acc[4][4];
#pragma unroll
    for (int i = 0; i < 4; i++)
#pragma unroll
        for (int j = 0; j < 4; j++) acc[i][j] = 0.f;

#pragma unroll
    for (int k = 0; k < 64; k++) {
        int s = k & 15;
        float4 a  = *(const float4*)&As[k * 64 + ((ty ^ s) << 2)];
        float4 bv = *(const float4*)&Bs[k * 64 + ((tx ^ s) << 2)];
        acc[0][0] = fmaf(a.x, bv.x, acc[0][0]); acc[0][1] = fmaf(a.x, bv.y, acc[0][1]);
        acc[0][2] = fmaf(a.x, bv.z, acc[0][2]); acc[0][3] = fmaf(a.x, bv.w, acc[0][3]);
        acc[1][0] = fmaf(a.y, bv.x, acc[1][0]); acc[1][1] = fmaf(a.y, bv.y, acc[1][1]);
        acc[1][2] = fmaf(a.y, bv.z, acc[1][2]); acc[1][3] = fmaf(a.y, bv.w, acc[1][3]);
        acc[2][0] = fmaf(a.z, bv.x, acc[2][0]); acc[2][1] = fmaf(a.z, bv.y, acc[2][1]);
        acc[2][2] = fmaf(a.z, bv.z, acc[2][2]); acc[2][3] = fmaf(a.z, bv.w, acc[2][3]);
        acc[3][0] = fmaf(a.w, bv.x, acc[3][0]); acc[3][1] = fmaf(a.w, bv.y, acc[3][1]);
        acc[3][2] = fmaf(a.w, bv.z, acc[3][2]); acc[3][3] = fmaf(a.w, bv.w, acc[3][3]);
    }

    float* Cb = C + (size_t)bz * (QQ * QQ) + (size_t)i0 * QQ + j0;
#pragma unroll
    for (int ii = 0; ii < 4; ii++) {
        *(float4*)&Cb[(size_t)(ty * 4 + ii) * QQ + tx * 4] =
            make_float4(acc[ii][0], acc[ii][1], acc[ii][2], acc[ii][3]);
    }
}

// ---------------- combine (AC + rel-shifted BD) * scale + softmax over k, in-place into AC ----
// Exact rel_shift semantics (no upper-triangle mask in the reference!):
//   shifted[i,j] = BD[i,   Q-1 + j - i]   for j <= i
//                = 0                      for j == i+1
//                = BD[i+1, j - i - 2]     for j >= i+2   (wrap into next row)
__global__ __launch_bounds__(256) void softmax_kernel(float* __restrict__ AC,
                                                      const float* __restrict__ BD) {
    __shared__ float sbuf[8];
    int row = blockIdx.x;             // bz*1024 + i
    int i = row & (QQ - 1);
    float* ac = AC + (size_t)row * QQ;
    const float* bd  = BD + (size_t)row * QQ;
    const float* bdn = bd + QQ;       // row i+1 (only touched when j >= i+2 => i <= Q-3)
    int t = threadIdx.x;
    float v[4]; float mx = -1e30f;
#pragma unroll
    for (int r = 0; r < 4; r++) {
        int j = t + r * 256;
        float s = ac[j];
        int d = j - i;
        if (d <= 0)      s += bd[(QQ - 1) + d];
        else if (d >= 2) s += bdn[d - 2];
        s *= 0.125f;                              // 1/sqrt(64)
        v[r] = s;
        mx = fmaxf(mx, s);
    }
    mx = blockMax(mx, sbuf);
    float sum = 0.f;
#pragma unroll
    for (int r = 0; r < 4; r++) { v[r] = __expf(v[r] - mx); sum += v[r]; }
    sum = blockSum(sum, sbuf);
    float inv = 1.0f / sum;
#pragma unroll
    for (int r = 0; r < 4; r++) ac[t + r * 256] = v[r] * inv;
}

// ---------------- batched P@V: out[i, b, h, d] = sum_j P[bz][i][j] * V[j,b,h,d] ----------------
__global__ __launch_bounds__(256) void pv_kernel(const float* __restrict__ P,
                                                 const float* __restrict__ QKV,
                                                 float* __restrict__ Out) {
    __shared__ float As[16][132];   // [k][i]
    __shared__ float Bs[16][68];    // [k][d]
    int t = threadIdx.x;
    int bz = blockIdx.z, b = bz >> 4, h = bz & 15;
    int i0 = blockIdx.x * 128;
    const float* Pb = P + (size_t)bz * (QQ * QQ);
    const float* Vb = QKV + 2048 + b * 3072 + h * 64;
    int tx = t & 15, ty = t >> 4;
    float acc[8][4];
#pragma unroll
    for (int i = 0; i < 8; i++)
#pragma unroll
        for (int j = 0; j < 4; j++) acc[i][j] = 0.f;

    for (int k0 = 0; k0 < QQ; k0 += 16) {
#pragma unroll
        for (int rep = 0; rep < 2; rep++) {
            int idx = t + rep * 256;
            int r = idx >> 2, c4 = (idx & 3) << 2;
            float4 v = *(const float4*)(Pb + (size_t)(i0 + r) * QQ + k0 + c4);
            As[c4 + 0][r] = v.x; As[c4 + 1][r] = v.y;
            As[c4 + 2][r] = v.z; As[c4 + 3][r] = v.w;
        }
        {
            int r = t >> 4, c4 = (t & 15) << 2;
            float4 v = *(const float4*)(Vb + (size_t)(k0 + r) * 24576 + c4);
            *(float4*)&Bs[r][c4] = v;
        }
        __syncthreads();
#pragma unroll
        for (int k = 0; k < 16; k++) {
            float a[8];
            *(float4*)(a)     = *(const float4*)&As[k][ty * 8];
            *(float4*)(a + 4) = *(const float4*)&As[k][ty * 8 + 4];
            float4 b4 = *(const float4*)&Bs[k][tx * 4];
#pragma unroll
            for (int ii = 0; ii < 8; ii++) {
                acc[ii][0] = fmaf(a[ii], b4.x, acc[ii][0]);
                acc[ii][1] = fmaf(a[ii], b4.y, acc[ii][1]);
                acc[ii][2] = fmaf(a[ii], b4.z, acc[ii][2]);
                acc[ii][3] = fmaf(a[ii], b4.w, acc[ii][3]);
            }
        }
        __syncthreads();
    }

    float* Ob = Out + b * DD + h * 64;
#pragma unroll
    for (int ii = 0; ii < 8; ii++) {
        int i = i0 + ty * 8 + ii;
        *(float4*)&Ob[(size_t)i * (BB * DD) + tx * 4] =
            make_float4(acc[ii][0], acc[ii][1], acc[ii][2], acc[ii][3]);
    }
}

// ---------------- host launch ----------------
extern "C" void kernel_launch(void* const* d_in, const int* in_sizes, int n_in,
                              void* d_out, int out_size) {
    (void)in_sizes; (void)n_in; (void)out_size;
    const float* x    = (const float*)d_in[0];
    const float* pos  = (const float*)d_in[1];
    /* d_in[2] = attn_mask: identically False -> unused */
    const float* ln1g = (const float*)d_in[3];
    const float* ln1b = (const float*)d_in[4];
    const float* qkvw = (const float*)d_in[5];
    const float* qkvb = (const float*)d_in[6];
    const float* rw   = (const float*)d_in[7];
    const float* rwb  = (const float*)d_in[8];
    const float* rrb  = (const float*)d_in[9];
    const float* ow   = (const float*)d_in[10];
    const float* ln2g = (const float*)d_in[11];
    const float* ln2b = (const float*)d_in[12];
    const float* w1   = (const float*)d_in[13];
    const float* b1   = (const float*)d_in[14];
    const float* w2   = (const float*)d_in[15];
    const float* b2   = (const float*)d_in[16];
    float* out = (float*)d_out;

    float *qkv, *qc, *qr, *rk, *AC, *BD, *y, *attn, *xa, *hid;
    cudaGetSymbolAddress((void**)&qkv,  g_qkv);
    cudaGetSymbolAddress((void**)&qc,   g_qc);
    cudaGetSymbolAddress((void**)&qr,   g_qr);
    cudaGetSymbolAddress((void**)&rk,   g_rk);
    cudaGetSymbolAddress((void**)&AC,   g_AC);
    cudaGetSymbolAddress((void**)&BD,   g_BD);
    cudaGetSymbolAddress((void**)&y,    g_y);
    cudaGetSymbolAddress((void**)&attn, g_attn);
    cudaGetSymbolAddress((void**)&xa,   g_xa);
    cudaGetSymbolAddress((void**)&hid,  g_hid);

    // 1. LN1
    ln_kernel<<<MM, 256>>>(x, ln1g, ln1b, y);
    // 2. QKV projection: [8192,1024]@[1024,3072]+b
    gemm_kernel<<<dim3(3 * DD / GBN, MM / GBM), 256>>>(y, qkvw, qkv, qkvb, nullptr,
                                                       MM, 3 * DD, DD, FL_BIAS);
    // 3. rk = pos_emb @ r_w : [1024,1024]@[1024,1024]
    gemm_kernel<<<dim3(DD / GBN, QQ / GBM), 256>>>(pos, rw, rk, nullptr, nullptr,
                                                   QQ, DD, DD, 0);
    // 4. qc = wq + r_w_bias, qr = wq + r_r_bias
    prep_kernel<<<MM, 256>>>(qkv, rwb, rrb, qc, qr);
    // 5. AC[bz][i][j] = qc . wk   (batched over 128 (b,h))
    score_kernel<<<dim3(16, 16, BB * HH), 256>>>(qc, DD, BB * DD,
                                                 qkv + DD, 3 * DD, BB * 3 * DD, AC);
    // 6. BD[bz][i][r] = qr . rk   (rk shared across b)
    score_kernel<<<dim3(16, 16, BB * HH), 256>>>(qr, DD, BB * DD,
                                                 rk, 0, DD, BD);
    // 7. combine + rel_shift (with wrap-around) + softmax -> probs (in-place in AC)
    softmax_kernel<<<BB * HH * QQ, 256>>>(AC, BD);
    // 8. attn_vec = P @ V
    pv_kernel<<<dim3(QQ / 128, 1, BB * HH), 256>>>(AC, qkv, attn);
    // 9. xa = x + attn @ o_w
    gemm_kernel<<<dim3(DD / GBN, MM / GBM), 256>>>(attn, ow, xa, nullptr, x,
                                                   MM, DD, DD, FL_RES);
    // 10. LN2
    ln_kernel<<<MM, 256>>>(xa, ln2g, ln2b, y);
    // 11. hid = relu(y @ w1 + b1)
    gemm_kernel<<<dim3(FFF / GBN, MM / GBM), 256>>>(y, w1, hid, b1, nullptr,
                                                    MM, FFF, DD, FL_BIAS | FL_RELU);
    // 12. out = xa + hid @ w2 + b2
    gemm_kernel<<<dim3(DD / GBN, MM / GBM), 256>>>(hid, w2, out, b2, xa,
                                                   MM, DD, FFF, FL_BIAS | FL_RES);
}

// round 3
// speedup vs baseline: 2.5584x; 2.5584x over previous
#include <cuda_runtime.h>
#include <math.h>
#include <stdint.h>

#define QQ 1024
#define BB 8
#define DD 1024
#define HH 16
#define DHH 64
#define FFF 4096
#define MM (QQ*BB)          /* 8192 rows (q*B+b) */

// ---------------- scratch ----------------
__device__ float g_qkv [(size_t)MM * 3 * DD];      // 96 MB  [m][3D]
__device__ float g_rk  [(size_t)QQ * DD];          // pos_emb @ r_w
__device__ float g_AC  [(size_t)BB * HH * QQ * QQ];// 512 MB scores / probs (in-place)
__device__ float g_BD  [(size_t)BB * HH * QQ * QQ];// 512 MB rel scores
__device__ float g_y   [(size_t)MM * DD];          // LN outputs (reused)
__device__ float g_attn[(size_t)MM * DD];          // attention output
__device__ float g_xa  [(size_t)MM * DD];          // x + attn@o_w
__device__ float g_hid [(size_t)MM * FFF];         // 128 MB FFN hidden

// ---------------- tf32 helpers ----------------
__device__ __forceinline__ uint32_t f2tf(float f) {
    uint32_t r; asm("cvt.rna.tf32.f32 %0, %1;" : "=r"(r) : "f"(f)); return r;
}
__device__ __forceinline__ void mma8(float* c, const uint32_t* a, const uint32_t* b) {
    asm volatile("mma.sync.aligned.m16n8k8.row.col.f32.tf32.tf32.f32 "
                 "{%0,%1,%2,%3}, {%4,%5,%6,%7}, {%8,%9}, {%0,%1,%2,%3};"
                 : "+f"(c[0]), "+f"(c[1]), "+f"(c[2]), "+f"(c[3])
                 : "r"(a[0]), "r"(a[1]), "r"(a[2]), "r"(a[3]), "r"(b[0]), "r"(b[1]));
}

// ---------------- block reductions ----------------
__device__ __forceinline__ float blockSum(float v, float* sbuf) {
    int t = threadIdx.x;
#pragma unroll
    for (int o = 16; o > 0; o >>= 1) v += __shfl_xor_sync(0xffffffffu, v, o);
    __syncthreads();
    if ((t & 31) == 0) sbuf[t >> 5] = v;
    __syncthreads();
    float s = 0.f;
#pragma unroll
    for (int w = 0; w < 8; w++) s += sbuf[w];
    return s;
}
__device__ __forceinline__ float blockMax(float v, float* sbuf) {
    int t = threadIdx.x;
#pragma unroll
    for (int o = 16; o > 0; o >>= 1) v = fmaxf(v, __shfl_xor_sync(0xffffffffu, v, o));
    __syncthreads();
    if ((t & 31) == 0) sbuf[t >> 5] = v;
    __syncthreads();
    float s = -1e30f;
#pragma unroll
    for (int w = 0; w < 8; w++) s = fmaxf(s, sbuf[w]);
    return s;
}

// ---------------- LayerNorm ----------------
__global__ __launch_bounds__(256) void ln_kernel(const float* __restrict__ X,
                                                 const float* __restrict__ g,
                                                 const float* __restrict__ b,
                                                 float* __restrict__ Y) {
    __shared__ float sbuf[8];
    int row = blockIdx.x, t = threadIdx.x;
    const float* xr = X + (size_t)row * DD;
    float v[4]; float s = 0.f;
#pragma unroll
    for (int r = 0; r < 4; r++) { v[r] = xr[t + r * 256]; s += v[r]; }
    s = blockSum(s, sbuf);
    float mu = s * (1.0f / DD);
    float s2 = 0.f;
#pragma unroll
    for (int r = 0; r < 4; r++) { v[r] -= mu; s2 += v[r] * v[r]; }
    s2 = blockSum(s2, sbuf);
    float rs = rsqrtf(s2 * (1.0f / DD) + 1e-5f);
    float* yr = Y + (size_t)row * DD;
#pragma unroll
    for (int r = 0; r < 4; r++) {
        int j = t + r * 256;
        yr[j] = v[r] * rs * g[j] + b[j];
    }
}

// =======================================================================================
// Dense tf32 tensor-core GEMM: C[M,N] = A[M,K] @ W[K,N]  (+bias)(+relu)(+res)
// Block 128x128, KT=32, 256 threads = 8 warps (2x4), warp tile 64x32 (4x4 m16n8 tiles).
// =======================================================================================
#define FL_BIAS 1
#define FL_RELU 2
#define FL_RES  4

__global__ __launch_bounds__(256, 2) void gemm_tc(const float* __restrict__ A,
                                                  const float* __restrict__ W,
                                                  float* __restrict__ C,
                                                  const float* __restrict__ bias,
                                                  const float* __restrict__ res,
                                                  int M, int N, int K, int flags) {
    __shared__ uint32_t As[128 * 36];   // [m][k], pad 36 -> frag banks 4g+tg (conflict-free)
    __shared__ uint32_t Bs[32 * 136];   // [k][n], pad 136 -> frag banks 8tg+g (conflict-free)
    int t = threadIdx.x;
    int m0 = blockIdx.y * 128, n0 = blockIdx.x * 128;
    int w = t >> 5, lane = t & 31, g = lane >> 2, tg = lane & 3;
    int wm = (w >> 2) * 64, wn = (w & 3) * 32;

    float c[4][4][4];
#pragma unroll
    for (int i = 0; i < 4; i++)
#pragma unroll
        for (int j = 0; j < 4; j++)
#pragma unroll
            for (int e = 0; e < 4; e++) c[i][j][e] = 0.f;

    for (int k0 = 0; k0 < K; k0 += 32) {
#pragma unroll
        for (int r = 0; r < 4; r++) {                       // A: 128x32
            int id = t + r * 256;
            int row = id >> 3, c4 = (id & 7) << 2;
            float4 v = *(const float4*)(A + (size_t)(m0 + row) * K + k0 + c4);
            uint4 u = make_uint4(f2tf(v.x), f2tf(v.y), f2tf(v.z), f2tf(v.w));
            *(uint4*)&As[row * 36 + c4] = u;
        }
#pragma unroll
        for (int r = 0; r < 4; r++) {                       // B: 32x128
            int id = t + r * 256;
            int row = id >> 5, c4 = (id & 31) << 2;
            float4 v = *(const float4*)(W + (size_t)(k0 + row) * N + n0 + c4);
            uint4 u = make_uint4(f2tf(v.x), f2tf(v.y), f2tf(v.z), f2tf(v.w));
            *(uint4*)&Bs[row * 136 + c4] = u;
        }
        __syncthreads();
#pragma unroll
        for (int ks = 0; ks < 4; ks++) {
            uint32_t af[4][4], bf[4][2];
            int kc = ks * 8 + tg;
#pragma unroll
            for (int mt = 0; mt < 4; mt++) {
                int mr = wm + mt * 16 + g;
                af[mt][0] = As[mr * 36 + kc];
                af[mt][1] = As[(mr + 8) * 36 + kc];
                af[mt][2] = As[mr * 36 + kc + 4];
                af[mt][3] = As[(mr + 8) * 36 + kc + 4];
            }
#pragma unroll
            for (int nt = 0; nt < 4; nt++) {
                int nc = wn + nt * 8 + g;
                bf[nt][0] = Bs[kc * 136 + nc];
                bf[nt][1] = Bs[(kc + 4) * 136 + nc];
            }
#pragma unroll
            for (int mt = 0; mt < 4; mt++)
#pragma unroll
                for (int nt = 0; nt < 4; nt++)
                    mma8(c[mt][nt], af[mt], bf[nt]);
        }
        __syncthreads();
    }

#pragma unroll
    for (int mt = 0; mt < 4; mt++) {
        int r0 = m0 + wm + mt * 16 + g;
#pragma unroll
        for (int nt = 0; nt < 4; nt++) {
            int col = n0 + wn + nt * 8 + 2 * tg;
            float2 p0 = make_float2(c[mt][nt][0], c[mt][nt][1]);
            float2 p1 = make_float2(c[mt][nt][2], c[mt][nt][3]);
            if (flags & FL_BIAS) {
                float2 bv = *(const float2*)(bias + col);
                p0.x += bv.x; p0.y += bv.y; p1.x += bv.x; p1.y += bv.y;
            }
            if (flags & FL_RELU) {
                p0.x = fmaxf(p0.x, 0.f); p0.y = fmaxf(p0.y, 0.f);
                p1.x = fmaxf(p1.x, 0.f); p1.y = fmaxf(p1.y, 0.f);
            }
            if (flags & FL_RES) {
                float2 q0 = *(const float2*)(res + (size_t)r0 * N + col);
                float2 q1 = *(const float2*)(res + (size_t)(r0 + 8) * N + col);
                p0.x += q0.x; p0.y += q0.y; p1.x += q1.x; p1.y += q1.y;
            }
            *(float2*)(C + (size_t)r0 * N + col) = p0;
            *(float2*)(C + (size_t)(r0 + 8) * N + col) = p1;
        }
    }
}

// =======================================================================================
// Batched score GEMM (tf32): C[bz][i][j] = sum_d (A[i,d]+abias[h*64+d]) * B[j,d], K=64
// A elem: A + b*a_bs + h*64 + i*a_rs + d ;  B elem: Bm + b*b_bs + h*64 + j*b_rs + d
// Block 128x128, two K half-tiles of 32.
// =======================================================================================
__global__ __launch_bounds__(256, 2) void score_tc(const float* __restrict__ A, int a_bs, int a_rs,
                                                   const float* __restrict__ abias,
                                                   const float* __restrict__ Bm, int b_bs, int b_rs,
                                                   float* __restrict__ C) {
    __shared__ uint32_t As[128 * 36];   // [i][k]
    __shared__ uint32_t Bs[128 * 36];   // [j][k]  (B row-major == col-major for mma)
    int t = threadIdx.x;
    int bz = blockIdx.z, b = bz >> 4, h = bz & 15;
    int i0 = blockIdx.y << 7, j0 = blockIdx.x << 7;
    const float* Ab = A + (size_t)b * a_bs + h * 64;
    const float* Bb = Bm + (size_t)b * b_bs + h * 64;
    const float* biash = abias + h * 64;
    int w = t >> 5, lane = t & 31, g = lane >> 2, tg = lane & 3;
    int wm = (w >> 2) * 64, wn = (w & 3) * 32;

    float c[4][4][4];
#pragma unroll
    for (int i = 0; i < 4; i++)
#pragma unroll
        for (int j = 0; j < 4; j++)
#pragma unroll
            for (int e = 0; e < 4; e++) c[i][j][e] = 0.f;

#pragma unroll
    for (int k0 = 0; k0 < 64; k0 += 32) {
#pragma unroll
        for (int r = 0; r < 4; r++) {
            int id = t + r * 256;
            int row = id >> 3, c4 = (id & 7) << 2;
            float4 va = *(const float4*)(Ab + (size_t)(i0 + row) * a_rs + k0 + c4);
            float4 bi = *(const float4*)(biash + k0 + c4);
            uint4 ua = make_uint4(f2tf(va.x + bi.x), f2tf(va.y + bi.y),
                                  f2tf(va.z + bi.z), f2tf(va.w + bi.w));
            *(uint4*)&As[row * 36 + c4] = ua;
            float4 vb = *(const float4*)(Bb + (size_t)(j0 + row) * b_rs + k0 + c4);
            uint4 ub = make_uint4(f2tf(vb.x), f2tf(vb.y), f2tf(vb.z), f2tf(vb.w));
            *(uint4*)&Bs[row * 36 + c4] = ub;
        }
        __syncthreads();
#pragma unroll
        for (int ks = 0; ks < 4; ks++) {
            uint32_t af[4][4], bf[4][2];
            int kc = ks * 8 + tg;
#pragma unroll
            for (int mt = 0; mt < 4; mt++) {
                int mr = wm + mt * 16 + g;
                af[mt][0] = As[mr * 36 + kc];
                af[mt][1] = As[(mr + 8) * 36 + kc];
                af[mt][2] = As[mr * 36 + kc + 4];
                af[mt][3] = As[(mr + 8) * 36 + kc + 4];
            }
#pragma unroll
            for (int nt = 0; nt < 4; nt++) {
                int nc = wn + nt * 8 + g;
                bf[nt][0] = Bs[nc * 36 + kc];
                bf[nt][1] = Bs[nc * 36 + kc + 4];
            }
#pragma unroll
            for (int mt = 0; mt < 4; mt++)
#pragma unroll
                for (int nt = 0; nt < 4; nt++)
                    mma8(c[mt][nt], af[mt], bf[nt]);
        }
        __syncthreads();
    }

    float* Cb = C + (size_t)bz * (QQ * QQ);
#pragma unroll
    for (int mt = 0; mt < 4; mt++) {
        int r0 = i0 + wm + mt * 16 + g;
#pragma unroll
        for (int nt = 0; nt < 4; nt++) {
            int col = j0 + wn + nt * 8 + 2 * tg;
            *(float2*)(Cb + (size_t)r0 * QQ + col) = make_float2(c[mt][nt][0], c[mt][nt][1]);
            *(float2*)(Cb + (size_t)(r0 + 8) * QQ + col) = make_float2(c[mt][nt][2], c[mt][nt][3]);
        }
    }
}

// ---------------- combine (AC + rel-shifted BD) * scale + softmax, in-place into AC ----
// shifted[i,j] = BD[i, Q-1+j-i] (j<=i) ; 0 (j==i+1) ; BD[i+1, j-i-2] (j>=i+2)
__global__ __launch_bounds__(256) void softmax_kernel(float* __restrict__ AC,
                                                      const float* __restrict__ BD) {
    __shared__ float sbuf[8];
    int row = blockIdx.x;             // bz*1024 + i
    int i = row & (QQ - 1);
    float* ac = AC + (size_t)row * QQ;
    const float* bd  = BD + (size_t)row * QQ;
    const float* bdn = bd + QQ;
    int t = threadIdx.x;
    float v[4]; float mx = -1e30f;
#pragma unroll
    for (int r = 0; r < 4; r++) {
        int j = t + r * 256;
        float s = ac[j];
        int d = j - i;
        if (d <= 0)      s += bd[(QQ - 1) + d];
        else if (d >= 2) s += bdn[d - 2];
        s *= 0.125f;
        v[r] = s;
        mx = fmaxf(mx, s);
    }
    mx = blockMax(mx, sbuf);
    float sum = 0.f;
#pragma unroll
    for (int r = 0; r < 4; r++) { v[r] = __expf(v[r] - mx); sum += v[r]; }
    sum = blockSum(sum, sbuf);
    float inv = 1.0f / sum;
#pragma unroll
    for (int r = 0; r < 4; r++) ac[t + r * 256] = v[r] * inv;
}

// =======================================================================================
// Batched P@V (tf32): out[i, b*1024+h*64+d] = sum_j P[bz][i][j] * V[j][d]
// Block 128(i) x 64(d), KT=32. 8 warps (2x4), warp tile 64x16 (4 m-tiles x 2 n-tiles).
// =======================================================================================
__global__ __launch_bounds__(256, 2) void pv_tc(const float* __restrict__ P,
                                                const float* __restrict__ QKV,
                                                float* __restrict__ Out) {
    __shared__ uint32_t As[128 * 36];  // P [i][j]
    __shared__ uint32_t Bs[32 * 72];   // V [k][d], pad 72 -> banks 8tg+g
    int t = threadIdx.x;
    int bz = blockIdx.z, b = bz >> 4, h = bz & 15;
    int i0 = blockIdx.x << 7;
    const float* Pb = P + (size_t)bz * (QQ * QQ);
    const float* Vb = QKV + 2048 + b * 3072 + h * 64;
    int w = t >> 5, lane = t & 31, g = lane >> 2, tg = lane & 3;
    int wm = (w >> 2) * 64, wn = (w & 3) * 16;

    float c[4][2][4];
#pragma unroll
    for (int i = 0; i < 4; i++)
#pragma unroll
        for (int j = 0; j < 2; j++)
#pragma unroll
            for (int e = 0; e < 4; e++) c[i][j][e] = 0.f;

    for (int k0 = 0; k0 < QQ; k0 += 32) {
#pragma unroll
        for (int r = 0; r < 4; r++) {                     // P tile 128x32
            int id = t + r * 256;
            int row = id >> 3, c4 = (id & 7) << 2;
            float4 v = *(const float4*)(Pb + (size_t)(i0 + row) * QQ + k0 + c4);
            uint4 u = make_uint4(f2tf(v.x), f2tf(v.y), f2tf(v.z), f2tf(v.w));
            *(uint4*)&As[row * 36 + c4] = u;
        }
        if (t < 128) {                                    // V tile 32x64
            int row = t >> 2, c4 = (t & 3) << 4;          // 16 floats per... (4 f4 slots)
            // simpler: 128 float4s: row = t>>2 gives 32 rows, 4 f4 each (64 floats)
            int cc = (t & 3) << 2;                        // f4 index 0..3 -> col base cc*?  (col = cc*1? )
            // col base actually (t&3)*16? 64 cols / 4 threads = 16 cols each
            float4 v = *(const float4*)(Vb + (size_t)(k0 + row) * 24576 + c4);
            uint4 u = make_uint4(f2tf(v.x), f2tf(v.y), f2tf(v.z), f2tf(v.w));
            *(uint4*)&Bs[row * 72 + c4] = u;
            v = *(const float4*)(Vb + (size_t)(k0 + row) * 24576 + c4 + 4);
            u = make_uint4(f2tf(v.x), f2tf(v.y), f2tf(v.z), f2tf(v.w));
            *(uint4*)&Bs[row * 72 + c4 + 4] = u;
            v = *(const float4*)(Vb + (size_t)(k0 + row) * 24576 + c4 + 8);
            u = make_uint4(f2tf(v.x), f2tf(v.y), f2tf(v.z), f2tf(v.w));
            *(uint4*)&Bs[row * 72 + c4 + 8] = u;
            v = *(const float4*)(Vb + (size_t)(k0 + row) * 24576 + c4 + 12);
            u = make_uint4(f2tf(v.x), f2tf(v.y), f2tf(v.z), f2tf(v.w));
            *(uint4*)&Bs[row * 72 + c4 + 12] = u;
            (void)cc;
        }
        __syncthreads();
#pragma unroll
        for (int ks = 0; ks < 4; ks++) {
            uint32_t af[4][4], bf[2][2];
            int kc = ks * 8 + tg;
#pragma unroll
            for (int mt = 0; mt < 4; mt++) {
                int mr = wm + mt * 16 + g;
                af[mt][0] = As[mr * 36 + kc];
                af[mt][1] = As[(mr + 8) * 36 + kc];
                af[mt][2] = As[mr * 36 + kc + 4];
                af[mt][3] = As[(mr + 8) * 36 + kc + 4];
            }
#pragma unroll
            for (int nt = 0; nt < 2; nt++) {
                int nc = wn + nt * 8 + g;
                bf[nt][0] = Bs[kc * 72 + nc];
                bf[nt][1] = Bs[(kc + 4) * 72 + nc];
            }
#pragma unroll
            for (int mt = 0; mt < 4; mt++)
#pragma unroll
                for (int nt = 0; nt < 2; nt++)
                    mma8(c[mt][nt], af[mt], bf[nt]);
        }
        __syncthreads();
    }

    float* Ob = Out + b * DD + h * 64;
#pragma unroll
    for (int mt = 0; mt < 4; mt++) {
        int r0 = i0 + wm + mt * 16 + g;
#pragma unroll
        for (int nt = 0; nt < 2; nt++) {
            int col = wn + nt * 8 + 2 * tg;
            *(float2*)(Ob + (size_t)r0 * (BB * DD) + col) = make_float2(c[mt][nt][0], c[mt][nt][1]);
            *(float2*)(Ob + (size_t)(r0 + 8) * (BB * DD) + col) = make_float2(c[mt][nt][2], c[mt][nt][3]);
        }
    }
}

// ---------------- host launch ----------------
extern "C" void kernel_launch(void* const* d_in, const int* in_sizes, int n_in,
                              void* d_out, int out_size) {
    (void)in_sizes; (void)n_in; (void)out_size;
    const float* x    = (const float*)d_in[0];
    const float* pos  = (const float*)d_in[1];
    /* d_in[2] = attn_mask: identically False -> unused */
    const float* ln1g = (const float*)d_in[3];
    const float* ln1b = (const float*)d_in[4];
    const float* qkvw = (const float*)d_in[5];
    const float* qkvb = (const float*)d_in[6];
    const float* rw   = (const float*)d_in[7];
    const float* rwb  = (const float*)d_in[8];
    const float* rrb  = (const float*)d_in[9];
    const float* ow   = (const float*)d_in[10];
    const float* ln2g = (const float*)d_in[11];
    const float* ln2b = (const float*)d_in[12];
    const float* w1   = (const float*)d_in[13];
    const float* b1   = (const float*)d_in[14];
    const float* w2   = (const float*)d_in[15];
    const float* b2   = (const float*)d_in[16];
    float* out = (float*)d_out;

    float *qkv, *rk, *AC, *BD, *y, *attn, *xa, *hid;
    cudaGetSymbolAddress((void**)&qkv,  g_qkv);
    cudaGetSymbolAddress((void**)&rk,   g_rk);
    cudaGetSymbolAddress((void**)&AC,   g_AC);
    cudaGetSymbolAddress((void**)&BD,   g_BD);
    cudaGetSymbolAddress((void**)&y,    g_y);
    cudaGetSymbolAddress((void**)&attn, g_attn);
    cudaGetSymbolAddress((void**)&xa,   g_xa);
    cudaGetSymbolAddress((void**)&hid,  g_hid);

    // 1. LN1
    ln_kernel<<<MM, 256>>>(x, ln1g, ln1b, y);
    // 2. QKV projection: [8192,1024]@[1024,3072]+b
    gemm_tc<<<dim3(3 * DD / 128, MM / 128), 256>>>(y, qkvw, qkv, qkvb, nullptr,
                                                   MM, 3 * DD, DD, FL_BIAS);
    // 3. rk = pos_emb @ r_w
    gemm_tc<<<dim3(DD / 128, QQ / 128), 256>>>(pos, rw, rk, nullptr, nullptr,
                                               QQ, DD, DD, 0);
    // 4. AC = (wq + r_w_bias) . wk
    score_tc<<<dim3(8, 8, BB * HH), 256>>>(qkv, 3 * DD, BB * 3 * DD, rwb,
                                           qkv + DD, 3 * DD, BB * 3 * DD, AC);
    // 5. BD = (wq + r_r_bias) . rk
    score_tc<<<dim3(8, 8, BB * HH), 256>>>(qkv, 3 * DD, BB * 3 * DD, rrb,
                                           rk, 0, DD, BD);
    // 6. combine + rel_shift + softmax -> probs (in-place in AC)
    softmax_kernel<<<BB * HH * QQ, 256>>>(AC, BD);
    // 7. attn_vec = P @ V
    pv_tc<<<dim3(QQ / 128, 1, BB * HH), 256>>>(AC, qkv, attn);
    // 8. xa = x + attn @ o_w
    gemm_tc<<<dim3(DD / 128, MM / 128), 256>>>(attn, ow, xa, nullptr, x,
                                               MM, DD, DD, FL_RES);
    // 9. LN2
    ln_kernel<<<MM, 256>>>(xa, ln2g, ln2b, y);
    // 10. hid = relu(y @ w1 + b1)
    gemm_tc<<<dim3(FFF / 128, MM / 128), 256>>>(y, w1, hid, b1, nullptr,
                                                MM, FFF, DD, FL_BIAS | FL_RELU);
    // 11. out = xa + hid @ w2 + b2
    gemm_tc<<<dim3(DD / 128, MM / 128), 256>>>(hid, w2, out, b2, xa,
                                               MM, DD, FFF, FL_BIAS | FL_RES);
}